// round 9
// baseline (speedup 1.0000x reference)
#include <cuda_runtime.h>
#include <cuda_fp16.h>
#include <cstdint>

#define NUM_EMB 16384
#define BT      16384
#define D       64
#define N_TILE  128
#define NTILES  (NUM_EMB / N_TILE)     // 128
#define M_TILE  128
#define NCTA    (BT / M_TILE)          // 128
#define NBLK    (NUM_EMB / 16)         // 1024 16-code blocks
#define EPSF    1040.0f                // int-screen-domain capture window

// smem: A tokens [128 x 64B] | B double buffer [2 x 128 x 64B]
#define SM_A   0
#define SM_B0  8192
#define SM_B1  16384
#define SM_TOT 24576

// ---------------- device scratch ----------------
__device__ float    g_qcb[NUM_EMB * D];       // projected codebook fp32 (gather)
__device__ float    g_cn [NUM_EMB * D];       // normalized codebook fp32 (rescore)
__device__ uint32_t g_cbi[NUM_EMB * 16];      // normalized codebook s8 packed (screen)
__device__ __half   g_bmax[(size_t)BT * NBLK];   // per-token 16-code block maxes (32 MB)
__device__ float    g_bestval[BT];
__device__ int      g_idx[BT];
__device__ float    g_partials[128];
__device__ int      g_done;                   // zero-init; reset by last kCD block

// ---------------- helpers ----------------
__device__ __forceinline__ uint32_t smem_u32(const void* p) {
    uint32_t a;
    asm("{ .reg .u64 t; cvta.to.shared.u64 t, %1; cvt.u32.u64 %0, t; }" : "=r"(a) : "l"(p));
    return a;
}
// 16B-chunk XOR swizzle for 64B rows
__device__ __forceinline__ uint32_t swz4(uint32_t chunk, uint32_t row) {
    return chunk ^ ((row >> 1) & 3u);
}

#define LDSM_X4(r0, r1, r2, r3, addr) \
    asm volatile("ldmatrix.sync.aligned.m8n8.x4.shared.b16 {%0,%1,%2,%3}, [%4];" \
                 : "=r"(r0), "=r"(r1), "=r"(r2), "=r"(r3) : "r"(addr))

#define IMMA16832(c0, c1, c2, c3, a0, a1, a2, a3, b0, b1) \
    asm volatile("mma.sync.aligned.m16n8k32.row.col.s32.s8.s8.s32 " \
                 "{%0,%1,%2,%3}, {%4,%5,%6,%7}, {%8,%9}, {%0,%1,%2,%3};" \
                 : "+r"(c0), "+r"(c1), "+r"(c2), "+r"(c3) \
                 : "r"(a0), "r"(a1), "r"(a2), "r"(a3), "r"(b0), "r"(b1))

#define CP_ASYNC16(dst, src) \
    asm volatile("cp.async.cg.shared.global [%0], [%1], 16;" :: "r"(dst), "l"(src) : "memory")
#define CP_COMMIT()  asm volatile("cp.async.commit_group;" ::: "memory")
#define CP_WAIT1()   asm volatile("cp.async.wait_group 1;" ::: "memory")
#define CP_WAIT0()   asm volatile("cp.async.wait_group 0;" ::: "memory")

__device__ __forceinline__ uint32_t pack4s8(float a, float b, float c, float d) {
    int q0 = __float2int_rn(a), q1 = __float2int_rn(b);
    int q2 = __float2int_rn(c), q3 = __float2int_rn(d);
    return (uint32_t)(q0 & 255) | ((uint32_t)(q1 & 255) << 8) |
           ((uint32_t)(q2 & 255) << 16) | ((uint32_t)(q3 & 255) << 24);
}

// ================= kPrep: project + normalize; fp32 + s8 codebooks =================
__global__ void __launch_bounds__(256) kPrep(const float* __restrict__ cb,
                                             const float* __restrict__ pw,
                                             const float* __restrict__ pb) {
    __shared__ float pwT[64 * 64];
    __shared__ float qs [64 * 64];
    __shared__ float rnorm[64];
    const int tid = threadIdx.x;

    for (int i = tid; i < 4096; i += 256) {
        int c = i >> 6, k = i & 63;
        pwT[k * 64 + c] = pw[i];
    }
    __syncthreads();

    const int c  = tid & 63;
    const int rg = tid >> 6;
    const float bias = pb[c];

    // cache this thread's proj_w column in registers (reused across 16 rows)
    float pwc[64];
#pragma unroll
    for (int k = 0; k < 64; k++) pwc[k] = pwT[k * 64 + c];

    for (int rr = 0; rr < 16; rr++) {
        int lrow = rg * 16 + rr;
        int row  = blockIdx.x * 64 + lrow;
        const float4* cbr4 = (const float4*)(cb + (size_t)row * 64);
        float acc = bias;
#pragma unroll
        for (int k4 = 0; k4 < 16; k4++) {
            float4 t = __ldg(&cbr4[k4]);
            acc = fmaf(t.x, pwc[4 * k4],     acc);
            acc = fmaf(t.y, pwc[4 * k4 + 1], acc);
            acc = fmaf(t.z, pwc[4 * k4 + 2], acc);
            acc = fmaf(t.w, pwc[4 * k4 + 3], acc);
        }
        qs[lrow * 64 + c] = acc;
    }
    __syncthreads();

    if (tid < 64) {
        float s = 0.f;
#pragma unroll
        for (int k = 0; k < 64; k++) {
            float v = qs[tid * 64 + k];
            s = fmaf(v, v, s);
        }
        rnorm[tid] = 1.0f / fmaxf(sqrtf(s), 1e-12f);
    }
    __syncthreads();

    const int base = blockIdx.x * 4096;
    for (int i = tid; i < 4096; i += 256) {
        float v = qs[i];
        int row = i >> 6;
        g_qcb[base + i] = v;
        g_cn [base + i] = v * rnorm[row];
    }
    for (int i = tid; i < 1024; i += 256) {
        int row = i >> 4;
        int j4  = i & 15;
        const float* qr = qs + row * 64 + j4 * 4;
        float rn = rnorm[row] * 127.0f;
        g_cbi[(size_t)(blockIdx.x * 64 + row) * 16 + j4] =
            pack4s8(qr[0] * rn, qr[1] * rn, qr[2] * rn, qr[3] * rn);
    }
}

// ================= kMain: s8 IMMA screen, branchless block-max =================
__global__ void __launch_bounds__(256, 1) kMain(const float* __restrict__ z) {
    extern __shared__ char smem[];
    __shared__ __half s_bmax[128 * 8];
    const uint32_t sb = smem_u32(smem);
    const int tid  = threadIdx.x;
    const int lane = tid & 31;
    const int w    = tid >> 5;
    const int tokbase = blockIdx.x * M_TILE;

    // ---- token prep: normalize, quantize s8, swizzled smem A (64B rows) ----
    if (tid < 128) {
        const int token = tokbase + tid;
        const float4* z4 = (const float4*)(z + (size_t)token * D);
        float v[64];
        float s = 0.f;
#pragma unroll
        for (int j = 0; j < 16; j++) {
            float4 t = z4[j];
            v[4 * j] = t.x; v[4 * j + 1] = t.y; v[4 * j + 2] = t.z; v[4 * j + 3] = t.w;
            s += t.x * t.x + t.y * t.y + t.z * t.z + t.w * t.w;
        }
        const float inv = 127.0f / fmaxf(sqrtf(s), 1e-12f);
        const uint32_t rowbase = (uint32_t)tid * 64u;
#pragma unroll
        for (int j = 0; j < 16; j++) {
            uint32_t pk = pack4s8(v[4*j] * inv, v[4*j+1] * inv, v[4*j+2] * inv, v[4*j+3] * inv);
            uint32_t addr = rowbase + (swz4((uint32_t)(j >> 2), (uint32_t)tid) << 4) + (uint32_t)(j & 3) * 4u;
            *(uint32_t*)(smem + SM_A + addr) = pk;
        }
    }

#define FILL(stage, tile_)                                                        \
    do {                                                                          \
        _Pragma("unroll")                                                         \
        for (int i = 0; i < 2; i++) {                                             \
            int idx = tid + i * 256;                                              \
            uint32_t code = (uint32_t)idx >> 2;                                   \
            uint32_t ch   = (uint32_t)idx & 3u;                                   \
            uint32_t dst  = sb + (stage) + code * 64u + (swz4(ch, code) << 4);    \
            const char* src = (const char*)g_cbi + (size_t)(tile_) * 8192 + code * 64 + ch * 16; \
            CP_ASYNC16(dst, src);                                                 \
        }                                                                         \
        CP_COMMIT();                                                              \
    } while (0)

    FILL(SM_B0, 0);
    FILL(SM_B1, 1);
    __syncthreads();

    // ---- A fragments (persistent, 8 regs) ----
    uint32_t a[8];
    {
        const uint32_t row_l = (uint32_t)((lane & 7) | (((lane >> 3) & 1) << 3));
        const uint32_t arow  = (uint32_t)(w * 16) + row_l;
        const uint32_t cb0   = (uint32_t)(lane >> 4);
        uint32_t base = sb + SM_A + arow * 64u;
        LDSM_X4(a[0], a[1], a[2], a[3], base + (swz4(cb0,      arow) << 4));
        LDSM_X4(a[4], a[5], a[6], a[7], base + (swz4(2u + cb0, arow) << 4));
    }

    int best0 = -1000000000, best1 = -1000000000;
    const int tl0 = w * 16 + (lane >> 2);
    const int tl1 = tl0 + 8;

    for (int t = 0; t < NTILES; t++) {
        if (t + 1 < NTILES) { CP_WAIT1(); } else { CP_WAIT0(); }
        __syncthreads();
        const uint32_t Bb = sb + ((t & 1) ? SM_B1 : SM_B0);

#pragma unroll 1
        for (int nb = 0; nb < 16; nb += 2) {
            uint32_t bb[2][4];
#pragma unroll
            for (int u = 0; u < 2; u++) {
                const uint32_t crow = (uint32_t)((nb + u) * 8) + (uint32_t)(lane & 7);
                LDSM_X4(bb[u][0], bb[u][1], bb[u][2], bb[u][3],
                        Bb + crow * 64u + (swz4((uint32_t)(lane >> 3), crow) << 4));
            }

            int c0[4] = {0, 0, 0, 0}, c1[4] = {0, 0, 0, 0};
            IMMA16832(c0[0], c0[1], c0[2], c0[3], a[0], a[1], a[2], a[3], bb[0][0], bb[0][1]);
            IMMA16832(c0[0], c0[1], c0[2], c0[3], a[4], a[5], a[6], a[7], bb[0][2], bb[0][3]);
            IMMA16832(c1[0], c1[1], c1[2], c1[3], a[0], a[1], a[2], a[3], bb[1][0], bb[1][1]);
            IMMA16832(c1[0], c1[1], c1[2], c1[3], a[4], a[5], a[6], a[7], bb[1][2], bb[1][3]);

            // branchless 16-code block max (quad butterfly), running best
            int m0 = max(max(c0[0], c0[1]), max(c1[0], c1[1]));
            int m1 = max(max(c0[2], c0[3]), max(c1[2], c1[3]));
            m0 = max(m0, __shfl_xor_sync(0xFFFFFFFFu, m0, 1));
            m1 = max(m1, __shfl_xor_sync(0xFFFFFFFFu, m1, 1));
            m0 = max(m0, __shfl_xor_sync(0xFFFFFFFFu, m0, 2));
            m1 = max(m1, __shfl_xor_sync(0xFFFFFFFFu, m1, 2));
            best0 = max(best0, m0);
            best1 = max(best1, m1);
            const int blk8 = nb >> 1;
            if ((lane & 3) == 0) {
                s_bmax[tl0 * 8 + blk8] = __float2half_rn((float)m0);
                s_bmax[tl1 * 8 + blk8] = __float2half_rn((float)m1);
            }
        }
        __syncthreads();
        {
            const int r = tid >> 1, h = tid & 1;
            uint2 val = *(const uint2*)&s_bmax[r * 8 + h * 4];
            *(uint2*)(g_bmax + ((size_t)(tokbase + r) * NBLK + t * 8 + h * 4)) = val;
        }
        if (t + 2 < NTILES) FILL(((t & 1) ? SM_B1 : SM_B0), t + 2);
    }
#undef FILL

    if ((lane & 3) == 0) {
        g_bestval[tokbase + tl0] = (float)best0;
        g_bestval[tokbase + tl1] = (float)best1;
    }
}

// ================= kScan: threshold block maxes + exact fp32 rescore =================
__global__ void __launch_bounds__(128) kScan(const float* __restrict__ z,
                                             float* __restrict__ out, int out_size) {
    __shared__ int s_list[4][128];
    __shared__ int s_n[4];
    const int warp = threadIdx.x >> 5;
    const int lane = threadIdx.x & 31;
    const int token = blockIdx.x * 4 + warp;

    if (lane == 0) s_n[warp] = 0;
    __syncwarp();

    const float thr = g_bestval[token] - EPSF;
    const uint4* bm = (const uint4*)(g_bmax + (size_t)token * NBLK);
#pragma unroll
    for (int q = 0; q < 4; q++) {
        uint4 u = bm[lane * 4 + q];
        uint32_t words[4] = {u.x, u.y, u.z, u.w};
#pragma unroll
        for (int k = 0; k < 4; k++) {
            __half2 h2 = *(__half2*)&words[k];
            float f0 = __low2float(h2), f1 = __high2float(h2);
            int blk0 = lane * 32 + q * 8 + k * 2;
            if (f0 > thr) { int p = atomicAdd(&s_n[warp], 1); if (p < 128) s_list[warp][p] = blk0; }
            if (f1 > thr) { int p = atomicAdd(&s_n[warp], 1); if (p < 128) s_list[warp][p] = blk0 + 1; }
        }
    }
    __syncwarp();
    int nc = s_n[warp]; if (nc > 128) nc = 128;

    float bestd = -1e30f;
    int   bidx  = 0x7fffffff;
    const float4* z4 = (const float4*)(z + (size_t)token * D);
    for (int ci = 0; ci < nc; ci++) {
        const int blk = s_list[warp][ci];
        if (lane < 16) {
            const int code = blk * 16 + lane;
            const float4* cr = (const float4*)(g_cn + (size_t)code * D);
            float d0 = 0.f, d1 = 0.f, d2 = 0.f, d3 = 0.f;
#pragma unroll
            for (int j = 0; j < 16; j++) {
                float4 b = cr[j];
                float4 a = __ldg(&z4[j]);
                d0 = fmaf(a.x, b.x, d0);
                d1 = fmaf(a.y, b.y, d1);
                d2 = fmaf(a.z, b.z, d2);
                d3 = fmaf(a.w, b.w, d3);
            }
            float dot = (d0 + d1) + (d2 + d3);
            if (dot > bestd || (dot == bestd && code < bidx)) { bestd = dot; bidx = code; }
        }
    }
#pragma unroll
    for (int off = 16; off; off >>= 1) {
        float ov = __shfl_xor_sync(0xFFFFFFFFu, bestd, off);
        int   oi = __shfl_xor_sync(0xFFFFFFFFu, bidx, off);
        if (ov > bestd || (ov == bestd && oi < bidx)) { bestd = ov; bidx = oi; }
    }
    if (lane == 0) {
        g_idx[token] = bidx;
        const int off = BT * D + 1 + token;
        if (off < out_size) out[off] = (float)bidx;
    }
}

// ================= kCD: gather quantized + MSE + finalize loss =================
__global__ void __launch_bounds__(256) kCD(const float* __restrict__ z,
                                           float* __restrict__ out, int out_size) {
    __shared__ float red[256];
    __shared__ int s_last;
    const int tid = threadIdx.x;
    const float4* z4 = (const float4*)z;
    const float4* q4 = (const float4*)g_qcb;
    float4* o4 = (float4*)out;

    float ps = 0.f;
#pragma unroll
    for (int i = 0; i < 8; i++) {
        int g = blockIdx.x * 2048 + i * 256 + tid;
        int token = g >> 4;
        int idx = g_idx[token];
        float4 q = q4[idx * 16 + (g & 15)];
        float4 zz = z4[g];
        if (g * 4 + 3 < out_size) o4[g] = q;
        float dx = q.x - zz.x, dy = q.y - zz.y;
        float dz_ = q.z - zz.z, dw = q.w - zz.w;
        ps += dx * dx + dy * dy + dz_ * dz_ + dw * dw;
    }
    red[tid] = ps;
    __syncthreads();
    for (int st = 128; st > 0; st >>= 1) {
        if (tid < st) red[tid] += red[tid + st];
        __syncthreads();
    }
    if (tid == 0) {
        g_partials[blockIdx.x] = red[0];
        __threadfence();
        int prev = atomicAdd(&g_done, 1);
        s_last = (prev == 127);
    }
    __syncthreads();
    if (s_last) {
        __threadfence();
        if (tid < 128) red[tid] = g_partials[tid];
        __syncthreads();
        for (int st = 64; st > 0; st >>= 1) {
            if (tid < st) red[tid] += red[tid + st];
            __syncthreads();
        }
        if (tid == 0) {
            float loss = 1.25f * red[0] / (float)(BT * D);
            if (BT * D < out_size) out[BT * D] = loss;
            g_done = 0;   // reset for next graph replay
        }
    }
}

// ================= launch =================
extern "C" void kernel_launch(void* const* d_in, const int* in_sizes, int n_in,
                              void* d_out, int out_size) {
    const float* z  = (const float*)d_in[0];
    const float* cb = (const float*)d_in[1];
    const float* pw = (const float*)d_in[2];
    const float* pb = (const float*)d_in[3];
    // d_in[4] = scale: positive constant, cannot change argmin or any output value.
    float* out = (float*)d_out;

    cudaFuncSetAttribute(kMain, cudaFuncAttributeMaxDynamicSharedMemorySize, SM_TOT);

    kPrep<<<NUM_EMB / 64, 256>>>(cb, pw, pb);
    kMain<<<NCTA, 256, SM_TOT>>>(z);
    kScan<<<BT / 4, 128>>>(z, out, out_size);
    kCD<<<128, 256>>>(z, out, out_size);
}

// round 10
// speedup vs baseline: 3.2096x; 3.2096x over previous
#include <cuda_runtime.h>
#include <cuda_fp16.h>
#include <cstdint>

#define NUM_EMB 16384
#define BT      16384
#define D       64
#define N_TILE  128
#define NTILES  (NUM_EMB / N_TILE)     // 128
#define M_TILE  128
#define NCTA    (BT / M_TILE)          // 128
#define NBLK32  (NUM_EMB / 32)         // 512 32-code blocks
#define EPS     0.0035f

// smem: A tokens [128 x 128B] | B double buffer [2 x 128 x 128B]
#define SM_A   0
#define SM_B0  16384
#define SM_B1  32768
#define SM_TOT 49152

// ---------------- device scratch ----------------
__device__ float  g_qcb[NUM_EMB * D];      // projected codebook fp32 (gather)
__device__ float  g_cn [NUM_EMB * D];      // normalized codebook fp32 (rescore)
__device__ __half g_cbh[NUM_EMB * D];      // normalized codebook fp16 (screen)
__device__ __half g_bmax[(size_t)BT * NBLK32];  // 32-code block maxes (16 MB)
__device__ float  g_bestval[BT];
__device__ int    g_idx[BT];
__device__ float  g_partials[128];
__device__ int    g_done;                  // zero-init; reset by last kCD block

// ---------------- helpers ----------------
__device__ __forceinline__ uint32_t smem_u32(const void* p) {
    uint32_t a;
    asm("{ .reg .u64 t; cvta.to.shared.u64 t, %1; cvt.u32.u64 %0, t; }" : "=r"(a) : "l"(p));
    return a;
}
// 16B-chunk XOR swizzle within a 128B row
__device__ __forceinline__ uint32_t swz(uint32_t byte, uint32_t row) {
    return ((((byte) >> 4) ^ (row & 7u)) << 4) | (byte & 15u);
}

#define LDSM_X4(r0, r1, r2, r3, addr) \
    asm volatile("ldmatrix.sync.aligned.m8n8.x4.shared.b16 {%0,%1,%2,%3}, [%4];" \
                 : "=r"(r0), "=r"(r1), "=r"(r2), "=r"(r3) : "r"(addr))

#define MMA16816(c0, c1, c2, c3, a0, a1, a2, a3, b0, b1) \
    asm volatile("mma.sync.aligned.m16n8k16.row.col.f32.f16.f16.f32 " \
                 "{%0,%1,%2,%3}, {%4,%5,%6,%7}, {%8,%9}, {%0,%1,%2,%3};" \
                 : "+f"(c0), "+f"(c1), "+f"(c2), "+f"(c3) \
                 : "r"(a0), "r"(a1), "r"(a2), "r"(a3), "r"(b0), "r"(b1))

#define CP_ASYNC16(dst, src) \
    asm volatile("cp.async.cg.shared.global [%0], [%1], 16;" :: "r"(dst), "l"(src) : "memory")
#define CP_COMMIT()  asm volatile("cp.async.commit_group;" ::: "memory")
#define CP_WAIT1()   asm volatile("cp.async.wait_group 1;" ::: "memory")
#define CP_WAIT0()   asm volatile("cp.async.wait_group 0;" ::: "memory")

// ================= kPrep: project + normalize; fp32 + fp16 codebooks =================
__global__ void __launch_bounds__(256) kPrep(const float* __restrict__ cb,
                                             const float* __restrict__ pw,
                                             const float* __restrict__ pb) {
    __shared__ float pwT[64 * 64];
    __shared__ float qs [64 * 64];
    __shared__ float rnorm[64];
    const int tid = threadIdx.x;

    for (int i = tid; i < 4096; i += 256) {
        int c = i >> 6, k = i & 63;
        pwT[k * 64 + c] = pw[i];
    }
    __syncthreads();

    const int c  = tid & 63;
    const int rg = tid >> 6;
    const float bias = pb[c];

    float pwc[64];
#pragma unroll
    for (int k = 0; k < 64; k++) pwc[k] = pwT[k * 64 + c];

    for (int rr = 0; rr < 16; rr++) {
        int lrow = rg * 16 + rr;
        int row  = blockIdx.x * 64 + lrow;
        const float4* cbr4 = (const float4*)(cb + (size_t)row * 64);
        float acc = bias;
#pragma unroll
        for (int k4 = 0; k4 < 16; k4++) {
            float4 t = __ldg(&cbr4[k4]);
            acc = fmaf(t.x, pwc[4 * k4],     acc);
            acc = fmaf(t.y, pwc[4 * k4 + 1], acc);
            acc = fmaf(t.z, pwc[4 * k4 + 2], acc);
            acc = fmaf(t.w, pwc[4 * k4 + 3], acc);
        }
        qs[lrow * 64 + c] = acc;
    }
    __syncthreads();

    if (tid < 64) {
        float s = 0.f;
#pragma unroll
        for (int k = 0; k < 64; k++) {
            float v = qs[tid * 64 + k];
            s = fmaf(v, v, s);
        }
        rnorm[tid] = 1.0f / fmaxf(sqrtf(s), 1e-12f);
    }
    __syncthreads();

    const int base = blockIdx.x * 4096;
    for (int i = tid; i < 4096; i += 256) {
        float v = qs[i];
        int row = i >> 6;
        g_qcb[base + i] = v;
        float cn = v * rnorm[row];
        g_cn [base + i] = cn;
        g_cbh[base + i] = __float2half_rn(cn);
    }
}

// ================= kMain: hi-only HMMA screen, 32-code block maxes =================
__global__ void __launch_bounds__(256, 1) kMain(const float* __restrict__ z) {
    extern __shared__ char smem[];
    __shared__ __half s_bmax[128 * 4];   // [token_row][blk32] for current tile
    const uint32_t sb = smem_u32(smem);
    const int tid  = threadIdx.x;
    const int lane = tid & 31;
    const int w    = tid >> 5;
    const int tokbase = blockIdx.x * M_TILE;

    // ---- token prep: normalize, fp16 into swizzled smem A (128B rows) ----
    if (tid < 128) {
        const int token = tokbase + tid;
        const float4* z4 = (const float4*)(z + (size_t)token * D);
        float v[64];
        float s = 0.f;
#pragma unroll
        for (int j = 0; j < 16; j++) {
            float4 t = z4[j];
            v[4 * j] = t.x; v[4 * j + 1] = t.y; v[4 * j + 2] = t.z; v[4 * j + 3] = t.w;
            s += t.x * t.x + t.y * t.y + t.z * t.z + t.w * t.w;
        }
        const float inv = 1.0f / fmaxf(sqrtf(s), 1e-12f);
        const uint32_t rowbase = (uint32_t)tid * 128u;
#pragma unroll
        for (int j = 0; j < 32; j++) {
            __half2 hh = __halves2half2(__float2half_rn(v[2 * j] * inv),
                                        __float2half_rn(v[2 * j + 1] * inv));
            *(__half2*)(smem + SM_A + rowbase + swz(4u * j, (uint32_t)tid)) = hh;
        }
    }

#define FILL(stage, tile_)                                                        \
    do {                                                                          \
        for (int i = 0; i < 4; i++) {                                             \
            int idx = tid + i * 256;                                              \
            uint32_t code = (uint32_t)idx >> 3;                                   \
            uint32_t ch   = (uint32_t)idx & 7u;                                   \
            uint32_t dst  = sb + (stage) + code * 128u + ((ch ^ (code & 7u)) << 4); \
            const __half* src = g_cbh + ((size_t)(tile_) * N_TILE + code) * 64 + ch * 8; \
            CP_ASYNC16(dst, src);                                                 \
        }                                                                         \
        CP_COMMIT();                                                              \
    } while (0)

    FILL(SM_B0, 0);
    FILL(SM_B1, 1);
    __syncthreads();

    // ---- load A fragments (persistent, 16 regs) ----
    uint32_t ah[16];
    {
        const uint32_t arow = (uint32_t)(w * 16) + (uint32_t)((lane & 7) + ((lane >> 3) & 1) * 8);
        const uint32_t kx   = (uint32_t)(lane >> 4) * 16u;
        const uint32_t abase = sb + SM_A + arow * 128u;
#pragma unroll
        for (int j = 0; j < 4; j++)
            LDSM_X4(ah[4 * j], ah[4 * j + 1], ah[4 * j + 2], ah[4 * j + 3],
                    abase + swz(32u * j + kx, arow));
    }

    float best0 = -3.0f, best1 = -3.0f;
    const int tl0 = w * 16 + (lane >> 2);
    const int tl1 = tl0 + 8;

    const uint32_t brow_in = (uint32_t)(lane & 7);
    const uint32_t bkx     = (uint32_t)(lane >> 3) * 16u;

    for (int t = 0; t < NTILES; t++) {
        if (t + 1 < NTILES) { CP_WAIT1(); } else { CP_WAIT0(); }
        __syncthreads();
        const uint32_t Bb = sb + ((t & 1) ? SM_B1 : SM_B0);

#pragma unroll 1
        for (int nb = 0; nb < 16; nb += 4) {
            uint32_t bh[4][8];
#pragma unroll
            for (int u = 0; u < 4; u++) {
                const uint32_t brow = (uint32_t)((nb + u) * 8) + brow_in;
                const uint32_t bbase = Bb + brow * 128u;
                LDSM_X4(bh[u][0], bh[u][1], bh[u][2], bh[u][3], bbase + swz(0u  + bkx, brow));
                LDSM_X4(bh[u][4], bh[u][5], bh[u][6], bh[u][7], bbase + swz(64u + bkx, brow));
            }

            float c[4][4] = {{0.f,0.f,0.f,0.f},{0.f,0.f,0.f,0.f},
                             {0.f,0.f,0.f,0.f},{0.f,0.f,0.f,0.f}};
#pragma unroll
            for (int j = 0; j < 4; j++) {
#pragma unroll
                for (int u = 0; u < 4; u++)
                    MMA16816(c[u][0], c[u][1], c[u][2], c[u][3],
                             ah[4*j], ah[4*j+1], ah[4*j+2], ah[4*j+3],
                             bh[u][2*j], bh[u][2*j+1]);
            }

            // branchless 32-code block max (quad butterfly)
            float m0 = fmaxf(fmaxf(fmaxf(c[0][0], c[0][1]), fmaxf(c[1][0], c[1][1])),
                             fmaxf(fmaxf(c[2][0], c[2][1]), fmaxf(c[3][0], c[3][1])));
            float m1 = fmaxf(fmaxf(fmaxf(c[0][2], c[0][3]), fmaxf(c[1][2], c[1][3])),
                             fmaxf(fmaxf(c[2][2], c[2][3]), fmaxf(c[3][2], c[3][3])));
            m0 = fmaxf(m0, __shfl_xor_sync(0xFFFFFFFFu, m0, 1));
            m1 = fmaxf(m1, __shfl_xor_sync(0xFFFFFFFFu, m1, 1));
            m0 = fmaxf(m0, __shfl_xor_sync(0xFFFFFFFFu, m0, 2));
            m1 = fmaxf(m1, __shfl_xor_sync(0xFFFFFFFFu, m1, 2));
            best0 = fmaxf(best0, m0);
            best1 = fmaxf(best1, m1);
            const int blk32 = nb >> 2;
            if ((lane & 3) == 0) {
                s_bmax[tl0 * 4 + blk32] = __float2half_rn(m0);
                s_bmax[tl1 * 4 + blk32] = __float2half_rn(m1);
            }
        }
        __syncthreads();
        // dump this tile's block maxes: 256 threads, 2 halfs each
        {
            const int r = tid >> 1, h = tid & 1;
            uint32_t val = ((const uint32_t*)s_bmax)[r * 2 + h];
            *(uint32_t*)(g_bmax + ((size_t)(tokbase + r) * NBLK32 + t * 4 + h * 2)) = val;
        }
        if (t + 2 < NTILES) FILL(((t & 1) ? SM_B1 : SM_B0), t + 2);
    }
#undef FILL

    if ((lane & 3) == 0) {
        g_bestval[tokbase + tl0] = best0;
        g_bestval[tokbase + tl1] = best1;
    }
}

// ================= kScan: threshold 32-code block maxes + exact fp32 rescore =========
__global__ void __launch_bounds__(128) kScan(const float* __restrict__ z,
                                             float* __restrict__ out, int out_size) {
    __shared__ int s_list[4][64];
    __shared__ int s_n[4];
    const int warp = threadIdx.x >> 5;
    const int lane = threadIdx.x & 31;
    const int token = blockIdx.x * 4 + warp;

    if (lane == 0) s_n[warp] = 0;
    __syncwarp();

    const float thr = g_bestval[token] - EPS;
    const uint4* bm = (const uint4*)(g_bmax + (size_t)token * NBLK32);
    // lane covers 16 halfs = 2 uint4
#pragma unroll
    for (int q = 0; q < 2; q++) {
        uint4 u = bm[lane * 2 + q];
        uint32_t words[4] = {u.x, u.y, u.z, u.w};
#pragma unroll
        for (int k = 0; k < 4; k++) {
            __half2 h2 = *(__half2*)&words[k];
            float f0 = __low2float(h2), f1 = __high2float(h2);
            int blk0 = lane * 16 + q * 8 + k * 2;
            if (f0 > thr) { int p = atomicAdd(&s_n[warp], 1); if (p < 64) s_list[warp][p] = blk0; }
            if (f1 > thr) { int p = atomicAdd(&s_n[warp], 1); if (p < 64) s_list[warp][p] = blk0 + 1; }
        }
    }
    __syncwarp();
    int nc = s_n[warp]; if (nc > 64) nc = 64;

    float bestd = -1e30f;
    int   bidx  = 0x7fffffff;
    const float4* z4 = (const float4*)(z + (size_t)token * D);
    for (int ci = 0; ci < nc; ci++) {
        const int blk = s_list[warp][ci];
        const int code = blk * 32 + lane;       // full warp: 32 codes per block
        const float4* cr = (const float4*)(g_cn + (size_t)code * D);
        float d0 = 0.f, d1 = 0.f, d2 = 0.f, d3 = 0.f;
#pragma unroll
        for (int j = 0; j < 16; j++) {
            float4 b = cr[j];
            float4 a = __ldg(&z4[j]);
            d0 = fmaf(a.x, b.x, d0);
            d1 = fmaf(a.y, b.y, d1);
            d2 = fmaf(a.z, b.z, d2);
            d3 = fmaf(a.w, b.w, d3);
        }
        float dot = (d0 + d1) + (d2 + d3);
        if (dot > bestd || (dot == bestd && code < bidx)) { bestd = dot; bidx = code; }
    }
#pragma unroll
    for (int off = 16; off; off >>= 1) {
        float ov = __shfl_xor_sync(0xFFFFFFFFu, bestd, off);
        int   oi = __shfl_xor_sync(0xFFFFFFFFu, bidx, off);
        if (ov > bestd || (ov == bestd && oi < bidx)) { bestd = ov; bidx = oi; }
    }
    if (lane == 0) {
        g_idx[token] = bidx;
        const int off = BT * D + 1 + token;
        if (off < out_size) out[off] = (float)bidx;
    }
}

// ================= kCD: gather quantized + MSE + finalize loss =================
__global__ void __launch_bounds__(256) kCD(const float* __restrict__ z,
                                           float* __restrict__ out, int out_size) {
    __shared__ float red[256];
    __shared__ int s_last;
    const int tid = threadIdx.x;
    const float4* z4 = (const float4*)z;
    const float4* q4 = (const float4*)g_qcb;
    float4* o4 = (float4*)out;

    float ps = 0.f;
#pragma unroll
    for (int i = 0; i < 8; i++) {
        int g = blockIdx.x * 2048 + i * 256 + tid;
        int token = g >> 4;
        int idx = g_idx[token];
        float4 q = q4[idx * 16 + (g & 15)];
        float4 zz = z4[g];
        if (g * 4 + 3 < out_size) o4[g] = q;
        float dx = q.x - zz.x, dy = q.y - zz.y;
        float dz_ = q.z - zz.z, dw = q.w - zz.w;
        ps += dx * dx + dy * dy + dz_ * dz_ + dw * dw;
    }
    red[tid] = ps;
    __syncthreads();
    for (int st = 128; st > 0; st >>= 1) {
        if (tid < st) red[tid] += red[tid + st];
        __syncthreads();
    }
    if (tid == 0) {
        g_partials[blockIdx.x] = red[0];
        __threadfence();
        int prev = atomicAdd(&g_done, 1);
        s_last = (prev == 127);
    }
    __syncthreads();
    if (s_last) {
        __threadfence();
        if (tid < 128) red[tid] = g_partials[tid];
        __syncthreads();
        for (int st = 64; st > 0; st >>= 1) {
            if (tid < st) red[tid] += red[tid + st];
            __syncthreads();
        }
        if (tid == 0) {
            float loss = 1.25f * red[0] / (float)(BT * D);
            if (BT * D < out_size) out[BT * D] = loss;
            g_done = 0;   // reset for next graph replay
        }
    }
}

// ================= launch =================
extern "C" void kernel_launch(void* const* d_in, const int* in_sizes, int n_in,
                              void* d_out, int out_size) {
    const float* z  = (const float*)d_in[0];
    const float* cb = (const float*)d_in[1];
    const float* pw = (const float*)d_in[2];
    const float* pb = (const float*)d_in[3];
    // d_in[4] = scale: positive constant, cannot change argmin or any output value.
    float* out = (float*)d_out;

    cudaFuncSetAttribute(kMain, cudaFuncAttributeMaxDynamicSharedMemorySize, SM_TOT);

    kPrep<<<NUM_EMB / 64, 256>>>(cb, pw, pb);
    kMain<<<NCTA, 256, SM_TOT>>>(z);
    kScan<<<BT / 4, 128>>>(z, out, out_size);
    kCD<<<128, 256>>>(z, out, out_size);
}

// round 11
// speedup vs baseline: 3.4154x; 1.0641x over previous
#include <cuda_runtime.h>
#include <cuda_fp16.h>
#include <cstdint>

#define NUM_EMB 16384
#define BT      16384
#define D       64
#define N_TILE  128
#define NTILES  (NUM_EMB / N_TILE)     // 128
#define M_TILE  128
#define NCTA    (BT / M_TILE)          // 128
#define NBLK    (NUM_EMB / 16)         // 1024 16-code blocks
#define EPS     0.003f

// smem: A tokens [128 x 128B] | B double buffer [2 x 128 x 128B]
#define SM_A   0
#define SM_B0  16384
#define SM_B1  32768
#define SM_TOT 49152

// ---------------- device scratch ----------------
__device__ float  g_qcb[NUM_EMB * D];      // projected codebook fp32 (gather)
__device__ float  g_cn [NUM_EMB * D];      // normalized codebook fp32 (rescore)
__device__ __half g_cbh[NUM_EMB * D];      // normalized codebook fp16 (screen)
__device__ __half g_bmax[(size_t)BT * NBLK];  // per-token 16-code block maxes (32 MB)
__device__ float  g_bestval[BT];
__device__ int    g_idx[BT];
__device__ float  g_partials[128];
__device__ int    g_done;                  // zero-init; reset by last kCD block

// ---------------- helpers ----------------
__device__ __forceinline__ uint32_t smem_u32(const void* p) {
    uint32_t a;
    asm("{ .reg .u64 t; cvta.to.shared.u64 t, %1; cvt.u32.u64 %0, t; }" : "=r"(a) : "l"(p));
    return a;
}
// 16B-chunk XOR swizzle within a 128B row
__device__ __forceinline__ uint32_t swz(uint32_t byte, uint32_t row) {
    return ((((byte) >> 4) ^ (row & 7u)) << 4) | (byte & 15u);
}

#define LDSM_X4(r0, r1, r2, r3, addr) \
    asm volatile("ldmatrix.sync.aligned.m8n8.x4.shared.b16 {%0,%1,%2,%3}, [%4];" \
                 : "=r"(r0), "=r"(r1), "=r"(r2), "=r"(r3) : "r"(addr))

#define MMA16816(c0, c1, c2, c3, a0, a1, a2, a3, b0, b1) \
    asm volatile("mma.sync.aligned.m16n8k16.row.col.f32.f16.f16.f32 " \
                 "{%0,%1,%2,%3}, {%4,%5,%6,%7}, {%8,%9}, {%0,%1,%2,%3};" \
                 : "+f"(c0), "+f"(c1), "+f"(c2), "+f"(c3) \
                 : "r"(a0), "r"(a1), "r"(a2), "r"(a3), "r"(b0), "r"(b1))

#define CP_ASYNC16(dst, src) \
    asm volatile("cp.async.cg.shared.global [%0], [%1], 16;" :: "r"(dst), "l"(src) : "memory")
#define CP_COMMIT()  asm volatile("cp.async.commit_group;" ::: "memory")
#define CP_WAIT1()   asm volatile("cp.async.wait_group 1;" ::: "memory")
#define CP_WAIT0()   asm volatile("cp.async.wait_group 0;" ::: "memory")

// ================= kPrep: project + normalize; fp32 + fp16 codebooks =================
__global__ void __launch_bounds__(256) kPrep(const float* __restrict__ cb,
                                             const float* __restrict__ pw,
                                             const float* __restrict__ pb) {
    __shared__ float pwT[64 * 64];
    __shared__ float qs [64 * 64];
    __shared__ float rnorm[64];
    const int tid = threadIdx.x;

    for (int i = tid; i < 4096; i += 256) {
        int c = i >> 6, k = i & 63;
        pwT[k * 64 + c] = pw[i];
    }
    __syncthreads();

    const int c  = tid & 63;
    const int rg = tid >> 6;
    const float bias = pb[c];

    float pwc[64];
#pragma unroll
    for (int k = 0; k < 64; k++) pwc[k] = pwT[k * 64 + c];

    for (int rr = 0; rr < 16; rr++) {
        int lrow = rg * 16 + rr;
        int row  = blockIdx.x * 64 + lrow;
        const float4* cbr4 = (const float4*)(cb + (size_t)row * 64);
        float acc = bias;
#pragma unroll
        for (int k4 = 0; k4 < 16; k4++) {
            float4 t = __ldg(&cbr4[k4]);
            acc = fmaf(t.x, pwc[4 * k4],     acc);
            acc = fmaf(t.y, pwc[4 * k4 + 1], acc);
            acc = fmaf(t.z, pwc[4 * k4 + 2], acc);
            acc = fmaf(t.w, pwc[4 * k4 + 3], acc);
        }
        qs[lrow * 64 + c] = acc;
    }
    __syncthreads();

    if (tid < 64) {
        float s = 0.f;
#pragma unroll
        for (int k = 0; k < 64; k++) {
            float v = qs[tid * 64 + k];
            s = fmaf(v, v, s);
        }
        rnorm[tid] = 1.0f / fmaxf(sqrtf(s), 1e-12f);
    }
    __syncthreads();

    const int base = blockIdx.x * 4096;
    for (int i = tid; i < 4096; i += 256) {
        float v = qs[i];
        int row = i >> 6;
        g_qcb[base + i] = v;
        float cn = v * rnorm[row];
        g_cn [base + i] = cn;
        g_cbh[base + i] = __float2half_rn(cn);
    }
}

// ================= kMain: hi-only HMMA screen, branchless 16-code block-max =========
__global__ void __launch_bounds__(256, 1) kMain(const float* __restrict__ z) {
    extern __shared__ char smem[];
    __shared__ __half s_bmax[128 * 8];   // [token_row][blk8] for current tile
    const uint32_t sb = smem_u32(smem);
    const int tid  = threadIdx.x;
    const int lane = tid & 31;
    const int w    = tid >> 5;
    const int tokbase = blockIdx.x * M_TILE;

    // ---- token prep: normalize, fp16 into swizzled smem A (128B rows) ----
    if (tid < 128) {
        const int token = tokbase + tid;
        const float4* z4 = (const float4*)(z + (size_t)token * D);
        float v[64];
        float s = 0.f;
#pragma unroll
        for (int j = 0; j < 16; j++) {
            float4 t = z4[j];
            v[4 * j] = t.x; v[4 * j + 1] = t.y; v[4 * j + 2] = t.z; v[4 * j + 3] = t.w;
            s += t.x * t.x + t.y * t.y + t.z * t.z + t.w * t.w;
        }
        const float inv = 1.0f / fmaxf(sqrtf(s), 1e-12f);
        const uint32_t rowbase = (uint32_t)tid * 128u;
#pragma unroll
        for (int j = 0; j < 32; j++) {
            __half2 hh = __halves2half2(__float2half_rn(v[2 * j] * inv),
                                        __float2half_rn(v[2 * j + 1] * inv));
            *(__half2*)(smem + SM_A + rowbase + swz(4u * j, (uint32_t)tid)) = hh;
        }
    }

#define FILL(stage, tile_)                                                        \
    do {                                                                          \
        for (int i = 0; i < 4; i++) {                                             \
            int idx = tid + i * 256;                                              \
            uint32_t code = (uint32_t)idx >> 3;                                   \
            uint32_t ch   = (uint32_t)idx & 7u;                                   \
            uint32_t dst  = sb + (stage) + code * 128u + ((ch ^ (code & 7u)) << 4); \
            const __half* src = g_cbh + ((size_t)(tile_) * N_TILE + code) * 64 + ch * 8; \
            CP_ASYNC16(dst, src);                                                 \
        }                                                                         \
        CP_COMMIT();                                                              \
    } while (0)

    FILL(SM_B0, 0);
    FILL(SM_B1, 1);
    __syncthreads();

    // ---- load A fragments (persistent, 16 regs) ----
    uint32_t ah[16];
    {
        const uint32_t arow = (uint32_t)(w * 16) + (uint32_t)((lane & 7) + ((lane >> 3) & 1) * 8);
        const uint32_t kx   = (uint32_t)(lane >> 4) * 16u;
        const uint32_t abase = sb + SM_A + arow * 128u;
#pragma unroll
        for (int j = 0; j < 4; j++)
            LDSM_X4(ah[4 * j], ah[4 * j + 1], ah[4 * j + 2], ah[4 * j + 3],
                    abase + swz(32u * j + kx, arow));
    }

    float best0 = -3.0f, best1 = -3.0f;
    const int tl0 = w * 16 + (lane >> 2);
    const int tl1 = tl0 + 8;

    const uint32_t brow_in = (uint32_t)(lane & 7);
    const uint32_t bkx     = (uint32_t)(lane >> 3) * 16u;

    for (int t = 0; t < NTILES; t++) {
        if (t + 1 < NTILES) { CP_WAIT1(); } else { CP_WAIT0(); }
        __syncthreads();
        const uint32_t Bb = sb + ((t & 1) ? SM_B1 : SM_B0);

#pragma unroll 1
        for (int nb = 0; nb < 16; nb += 2) {
            uint32_t bh[2][8];
#pragma unroll
            for (int u = 0; u < 2; u++) {
                const uint32_t brow = (uint32_t)((nb + u) * 8) + brow_in;
                const uint32_t bbase = Bb + brow * 128u;
                LDSM_X4(bh[u][0], bh[u][1], bh[u][2], bh[u][3], bbase + swz(0u  + bkx, brow));
                LDSM_X4(bh[u][4], bh[u][5], bh[u][6], bh[u][7], bbase + swz(64u + bkx, brow));
            }

            float c[2][4] = {{0.f,0.f,0.f,0.f},{0.f,0.f,0.f,0.f}};
#pragma unroll
            for (int j = 0; j < 4; j++) {
#pragma unroll
                for (int u = 0; u < 2; u++)
                    MMA16816(c[u][0], c[u][1], c[u][2], c[u][3],
                             ah[4*j], ah[4*j+1], ah[4*j+2], ah[4*j+3],
                             bh[u][2*j], bh[u][2*j+1]);
            }

            // branchless 16-code block max (quad butterfly), running best
            float m0 = fmaxf(fmaxf(c[0][0], c[0][1]), fmaxf(c[1][0], c[1][1]));
            float m1 = fmaxf(fmaxf(c[0][2], c[0][3]), fmaxf(c[1][2], c[1][3]));
            m0 = fmaxf(m0, __shfl_xor_sync(0xFFFFFFFFu, m0, 1));
            m1 = fmaxf(m1, __shfl_xor_sync(0xFFFFFFFFu, m1, 1));
            m0 = fmaxf(m0, __shfl_xor_sync(0xFFFFFFFFu, m0, 2));
            m1 = fmaxf(m1, __shfl_xor_sync(0xFFFFFFFFu, m1, 2));
            best0 = fmaxf(best0, m0);
            best1 = fmaxf(best1, m1);
            const int blk8 = nb >> 1;
            if ((lane & 3) == 0) {
                s_bmax[tl0 * 8 + blk8] = __float2half_rn(m0);
                s_bmax[tl1 * 8 + blk8] = __float2half_rn(m1);
            }
        }
        __syncthreads();
        // dump this tile's block maxes: thread -> (row r, half h)
        {
            const int r = tid >> 1, h = tid & 1;
            uint2 val = *(const uint2*)&s_bmax[r * 8 + h * 4];
            *(uint2*)(g_bmax + ((size_t)(tokbase + r) * NBLK + t * 8 + h * 4)) = val;
        }
        if (t + 2 < NTILES) FILL(((t & 1) ? SM_B1 : SM_B0), t + 2);
    }
#undef FILL

    if ((lane & 3) == 0) {
        g_bestval[tokbase + tl0] = best0;
        g_bestval[tokbase + tl1] = best1;
    }
}

// ================= kScan: threshold block maxes + exact fp32 rescore =================
__global__ void __launch_bounds__(128) kScan(const float* __restrict__ z,
                                             float* __restrict__ out, int out_size) {
    __shared__ int s_list[4][128];
    __shared__ int s_n[4];
    const int warp = threadIdx.x >> 5;
    const int lane = threadIdx.x & 31;
    const int token = blockIdx.x * 4 + warp;

    if (lane == 0) s_n[warp] = 0;
    __syncwarp();

    const float thr = g_bestval[token] - EPS;
    const uint4* bm = (const uint4*)(g_bmax + (size_t)token * NBLK);
#pragma unroll
    for (int q = 0; q < 4; q++) {
        uint4 u = bm[lane * 4 + q];
        uint32_t words[4] = {u.x, u.y, u.z, u.w};
#pragma unroll
        for (int k = 0; k < 4; k++) {
            __half2 h2 = *(__half2*)&words[k];
            float f0 = __low2float(h2), f1 = __high2float(h2);
            int blk0 = lane * 32 + q * 8 + k * 2;
            if (f0 > thr) { int p = atomicAdd(&s_n[warp], 1); if (p < 128) s_list[warp][p] = blk0; }
            if (f1 > thr) { int p = atomicAdd(&s_n[warp], 1); if (p < 128) s_list[warp][p] = blk0 + 1; }
        }
    }
    __syncwarp();
    int nc = s_n[warp]; if (nc > 128) nc = 128;

    float bestd = -1e30f;
    int   bidx  = 0x7fffffff;
    const float4* z4 = (const float4*)(z + (size_t)token * D);
    for (int ci = 0; ci < nc; ci++) {
        const int blk = s_list[warp][ci];
        if (lane < 16) {
            const int code = blk * 16 + lane;
            const float4* cr = (const float4*)(g_cn + (size_t)code * D);
            float d0 = 0.f, d1 = 0.f, d2 = 0.f, d3 = 0.f;
#pragma unroll
            for (int j = 0; j < 16; j++) {
                float4 b = cr[j];
                float4 a = __ldg(&z4[j]);
                d0 = fmaf(a.x, b.x, d0);
                d1 = fmaf(a.y, b.y, d1);
                d2 = fmaf(a.z, b.z, d2);
                d3 = fmaf(a.w, b.w, d3);
            }
            float dot = (d0 + d1) + (d2 + d3);
            if (dot > bestd || (dot == bestd && code < bidx)) { bestd = dot; bidx = code; }
        }
    }
#pragma unroll
    for (int off = 16; off; off >>= 1) {
        float ov = __shfl_xor_sync(0xFFFFFFFFu, bestd, off);
        int   oi = __shfl_xor_sync(0xFFFFFFFFu, bidx, off);
        if (ov > bestd || (ov == bestd && oi < bidx)) { bestd = ov; bidx = oi; }
    }
    if (lane == 0) {
        g_idx[token] = bidx;
        const int off = BT * D + 1 + token;
        if (off < out_size) out[off] = (float)bidx;
    }
}

// ================= kCD: gather quantized + MSE + finalize loss =================
__global__ void __launch_bounds__(256) kCD(const float* __restrict__ z,
                                           float* __restrict__ out, int out_size) {
    __shared__ float red[256];
    __shared__ int s_last;
    const int tid = threadIdx.x;
    const float4* z4 = (const float4*)z;
    const float4* q4 = (const float4*)g_qcb;
    float4* o4 = (float4*)out;

    float ps = 0.f;
#pragma unroll
    for (int i = 0; i < 8; i++) {
        int g = blockIdx.x * 2048 + i * 256 + tid;
        int token = g >> 4;
        int idx = g_idx[token];
        float4 q = q4[idx * 16 + (g & 15)];
        float4 zz = z4[g];
        if (g * 4 + 3 < out_size) o4[g] = q;
        float dx = q.x - zz.x, dy = q.y - zz.y;
        float dz_ = q.z - zz.z, dw = q.w - zz.w;
        ps += dx * dx + dy * dy + dz_ * dz_ + dw * dw;
    }
    red[tid] = ps;
    __syncthreads();
    for (int st = 128; st > 0; st >>= 1) {
        if (tid < st) red[tid] += red[tid + st];
        __syncthreads();
    }
    if (tid == 0) {
        g_partials[blockIdx.x] = red[0];
        __threadfence();
        int prev = atomicAdd(&g_done, 1);
        s_last = (prev == 127);
    }
    __syncthreads();
    if (s_last) {
        __threadfence();
        if (tid < 128) red[tid] = g_partials[tid];
        __syncthreads();
        for (int st = 64; st > 0; st >>= 1) {
            if (tid < st) red[tid] += red[tid + st];
            __syncthreads();
        }
        if (tid == 0) {
            float loss = 1.25f * red[0] / (float)(BT * D);
            if (BT * D < out_size) out[BT * D] = loss;
            g_done = 0;   // reset for next graph replay
        }
    }
}

// ================= launch =================
extern "C" void kernel_launch(void* const* d_in, const int* in_sizes, int n_in,
                              void* d_out, int out_size) {
    const float* z  = (const float*)d_in[0];
    const float* cb = (const float*)d_in[1];
    const float* pw = (const float*)d_in[2];
    const float* pb = (const float*)d_in[3];
    // d_in[4] = scale: positive constant, cannot change argmin or any output value.
    float* out = (float*)d_out;

    cudaFuncSetAttribute(kMain, cudaFuncAttributeMaxDynamicSharedMemorySize, SM_TOT);

    kPrep<<<NUM_EMB / 64, 256>>>(cb, pw, pb);
    kMain<<<NCTA, 256, SM_TOT>>>(z);
    kScan<<<BT / 4, 128>>>(z, out, out_size);
    kCD<<<128, 256>>>(z, out, out_size);
}

// round 12
// speedup vs baseline: 4.0670x; 1.1908x over previous
#include <cuda_runtime.h>
#include <cuda_fp16.h>
#include <cstdint>

#define NUM_EMB 16384
#define BT      16384
#define D       64
#define N_TILE  128
#define NTILES  (NUM_EMB / N_TILE)     // 128 total tiles
#define NSPLIT  2
#define TILES_PER_SPLIT (NTILES / NSPLIT)  // 64
#define M_TILE  128
#define NBLK    (NUM_EMB / 16)         // 1024 16-code blocks
#define EPS     0.003f

// smem: A tokens [128 x 128B] | B double buffer [2 x 128 x 128B]
#define SM_A   0
#define SM_B0  16384
#define SM_B1  32768
#define SM_TOT 49152

// ---------------- device scratch ----------------
__device__ float  g_qcb[NUM_EMB * D];      // projected codebook fp32 (gather)
__device__ float  g_cn [NUM_EMB * D];      // normalized codebook fp32 (rescore)
__device__ __half g_cbh[NUM_EMB * D];      // normalized codebook fp16 (screen)
__device__ __half g_bmax[(size_t)BT * NBLK];  // per-token 16-code block maxes (32 MB)
__device__ float  g_bestval[NSPLIT * BT];
__device__ int    g_idx[BT];
__device__ float  g_partials[128];
__device__ int    g_done;                  // zero-init; reset by last kCD block

// ---------------- helpers ----------------
__device__ __forceinline__ uint32_t smem_u32(const void* p) {
    uint32_t a;
    asm("{ .reg .u64 t; cvta.to.shared.u64 t, %1; cvt.u32.u64 %0, t; }" : "=r"(a) : "l"(p));
    return a;
}
// 16B-chunk XOR swizzle within a 128B row
__device__ __forceinline__ uint32_t swz(uint32_t byte, uint32_t row) {
    return ((((byte) >> 4) ^ (row & 7u)) << 4) | (byte & 15u);
}

#define LDSM_X4(r0, r1, r2, r3, addr) \
    asm volatile("ldmatrix.sync.aligned.m8n8.x4.shared.b16 {%0,%1,%2,%3}, [%4];" \
                 : "=r"(r0), "=r"(r1), "=r"(r2), "=r"(r3) : "r"(addr))

#define MMA16816(c0, c1, c2, c3, a0, a1, a2, a3, b0, b1) \
    asm volatile("mma.sync.aligned.m16n8k16.row.col.f32.f16.f16.f32 " \
                 "{%0,%1,%2,%3}, {%4,%5,%6,%7}, {%8,%9}, {%0,%1,%2,%3};" \
                 : "+f"(c0), "+f"(c1), "+f"(c2), "+f"(c3) \
                 : "r"(a0), "r"(a1), "r"(a2), "r"(a3), "r"(b0), "r"(b1))

#define CP_ASYNC16(dst, src) \
    asm volatile("cp.async.cg.shared.global [%0], [%1], 16;" :: "r"(dst), "l"(src) : "memory")
#define CP_COMMIT()  asm volatile("cp.async.commit_group;" ::: "memory")
#define CP_WAIT1()   asm volatile("cp.async.wait_group 1;" ::: "memory")
#define CP_WAIT0()   asm volatile("cp.async.wait_group 0;" ::: "memory")

// ================= kPrep: project + normalize; fp32 + fp16 codebooks =================
__global__ void __launch_bounds__(256) kPrep(const float* __restrict__ cb,
                                             const float* __restrict__ pw,
                                             const float* __restrict__ pb) {
    __shared__ float pwT[64 * 64];
    __shared__ float qs [64 * 64];
    __shared__ float rnorm[64];
    const int tid = threadIdx.x;

    for (int i = tid; i < 4096; i += 256) {
        int c = i >> 6, k = i & 63;
        pwT[k * 64 + c] = pw[i];
    }
    __syncthreads();

    const int c  = tid & 63;
    const int rg = tid >> 6;
    const float bias = pb[c];

    float pwc[64];
#pragma unroll
    for (int k = 0; k < 64; k++) pwc[k] = pwT[k * 64 + c];

    for (int rr = 0; rr < 16; rr++) {
        int lrow = rg * 16 + rr;
        int row  = blockIdx.x * 64 + lrow;
        const float4* cbr4 = (const float4*)(cb + (size_t)row * 64);
        float acc = bias;
#pragma unroll
        for (int k4 = 0; k4 < 16; k4++) {
            float4 t = __ldg(&cbr4[k4]);
            acc = fmaf(t.x, pwc[4 * k4],     acc);
            acc = fmaf(t.y, pwc[4 * k4 + 1], acc);
            acc = fmaf(t.z, pwc[4 * k4 + 2], acc);
            acc = fmaf(t.w, pwc[4 * k4 + 3], acc);
        }
        qs[lrow * 64 + c] = acc;
    }
    __syncthreads();

    if (tid < 64) {
        float s = 0.f;
#pragma unroll
        for (int k = 0; k < 64; k++) {
            float v = qs[tid * 64 + k];
            s = fmaf(v, v, s);
        }
        rnorm[tid] = 1.0f / fmaxf(sqrtf(s), 1e-12f);
    }
    __syncthreads();

    const int base = blockIdx.x * 4096;
    for (int i = tid; i < 4096; i += 256) {
        float v = qs[i];
        int row = i >> 6;
        g_qcb[base + i] = v;
        float cn = v * rnorm[row];
        g_cn [base + i] = cn;
        g_cbh[base + i] = __float2half_rn(cn);
    }
}

// ================= kMain: hi-only HMMA screen over a code split =================
// grid (128 token-blocks, 2 splits), 256 threads, 2 CTAs/SM.
__global__ void __launch_bounds__(256, 2) kMain(const float* __restrict__ z) {
    extern __shared__ char smem[];
    __shared__ __half s_bmax[128 * 8];
    const uint32_t sb = smem_u32(smem);
    const int tid  = threadIdx.x;
    const int lane = tid & 31;
    const int w    = tid >> 5;
    const int tokbase = blockIdx.x * M_TILE;
    const int split   = blockIdx.y;
    const int t0      = split * TILES_PER_SPLIT;

    // ---- token prep: normalize, fp16 into swizzled smem A (128B rows) ----
    if (tid < 128) {
        const int token = tokbase + tid;
        const float4* z4 = (const float4*)(z + (size_t)token * D);
        float v[64];
        float s = 0.f;
#pragma unroll
        for (int j = 0; j < 16; j++) {
            float4 t = z4[j];
            v[4 * j] = t.x; v[4 * j + 1] = t.y; v[4 * j + 2] = t.z; v[4 * j + 3] = t.w;
            s += t.x * t.x + t.y * t.y + t.z * t.z + t.w * t.w;
        }
        const float inv = 1.0f / fmaxf(sqrtf(s), 1e-12f);
        const uint32_t rowbase = (uint32_t)tid * 128u;
#pragma unroll
        for (int j = 0; j < 32; j++) {
            __half2 hh = __halves2half2(__float2half_rn(v[2 * j] * inv),
                                        __float2half_rn(v[2 * j + 1] * inv));
            *(__half2*)(smem + SM_A + rowbase + swz(4u * j, (uint32_t)tid)) = hh;
        }
    }

#define FILL(stage, tile_)                                                        \
    do {                                                                          \
        for (int i = 0; i < 4; i++) {                                             \
            int idx = tid + i * 256;                                              \
            uint32_t code = (uint32_t)idx >> 3;                                   \
            uint32_t ch   = (uint32_t)idx & 7u;                                   \
            uint32_t dst  = sb + (stage) + code * 128u + ((ch ^ (code & 7u)) << 4); \
            const __half* src = g_cbh + ((size_t)(tile_) * N_TILE + code) * 64 + ch * 8; \
            CP_ASYNC16(dst, src);                                                 \
        }                                                                         \
        CP_COMMIT();                                                              \
    } while (0)

    FILL(SM_B0, t0);
    FILL(SM_B1, t0 + 1);
    __syncthreads();

    // ---- load A fragments (persistent, 16 regs) ----
    uint32_t ah[16];
    {
        const uint32_t arow = (uint32_t)(w * 16) + (uint32_t)((lane & 7) + ((lane >> 3) & 1) * 8);
        const uint32_t kx   = (uint32_t)(lane >> 4) * 16u;
        const uint32_t abase = sb + SM_A + arow * 128u;
#pragma unroll
        for (int j = 0; j < 4; j++)
            LDSM_X4(ah[4 * j], ah[4 * j + 1], ah[4 * j + 2], ah[4 * j + 3],
                    abase + swz(32u * j + kx, arow));
    }

    float best0 = -3.0f, best1 = -3.0f;
    const int tl0 = w * 16 + (lane >> 2);
    const int tl1 = tl0 + 8;

    const uint32_t brow_in = (uint32_t)(lane & 7);
    const uint32_t bkx     = (uint32_t)(lane >> 3) * 16u;

    for (int tt = 0; tt < TILES_PER_SPLIT; tt++) {
        const int t = t0 + tt;
        if (tt + 1 < TILES_PER_SPLIT) { CP_WAIT1(); } else { CP_WAIT0(); }
        __syncthreads();
        const uint32_t Bb = sb + ((tt & 1) ? SM_B1 : SM_B0);

#pragma unroll 1
        for (int nb = 0; nb < 16; nb += 2) {
            uint32_t bh[2][8];
#pragma unroll
            for (int u = 0; u < 2; u++) {
                const uint32_t brow = (uint32_t)((nb + u) * 8) + brow_in;
                const uint32_t bbase = Bb + brow * 128u;
                LDSM_X4(bh[u][0], bh[u][1], bh[u][2], bh[u][3], bbase + swz(0u  + bkx, brow));
                LDSM_X4(bh[u][4], bh[u][5], bh[u][6], bh[u][7], bbase + swz(64u + bkx, brow));
            }

            float c[2][4] = {{0.f,0.f,0.f,0.f},{0.f,0.f,0.f,0.f}};
#pragma unroll
            for (int j = 0; j < 4; j++) {
#pragma unroll
                for (int u = 0; u < 2; u++)
                    MMA16816(c[u][0], c[u][1], c[u][2], c[u][3],
                             ah[4*j], ah[4*j+1], ah[4*j+2], ah[4*j+3],
                             bh[u][2*j], bh[u][2*j+1]);
            }

            float m0 = fmaxf(fmaxf(c[0][0], c[0][1]), fmaxf(c[1][0], c[1][1]));
            float m1 = fmaxf(fmaxf(c[0][2], c[0][3]), fmaxf(c[1][2], c[1][3]));
            m0 = fmaxf(m0, __shfl_xor_sync(0xFFFFFFFFu, m0, 1));
            m1 = fmaxf(m1, __shfl_xor_sync(0xFFFFFFFFu, m1, 1));
            m0 = fmaxf(m0, __shfl_xor_sync(0xFFFFFFFFu, m0, 2));
            m1 = fmaxf(m1, __shfl_xor_sync(0xFFFFFFFFu, m1, 2));
            best0 = fmaxf(best0, m0);
            best1 = fmaxf(best1, m1);
            const int blk8 = nb >> 1;
            if ((lane & 3) == 0) {
                s_bmax[tl0 * 8 + blk8] = __float2half_rn(m0);
                s_bmax[tl1 * 8 + blk8] = __float2half_rn(m1);
            }
        }
        __syncthreads();
        {
            const int r = tid >> 1, h = tid & 1;
            uint2 val = *(const uint2*)&s_bmax[r * 8 + h * 4];
            *(uint2*)(g_bmax + ((size_t)(tokbase + r) * NBLK + t * 8 + h * 4)) = val;
        }
        if (tt + 2 < TILES_PER_SPLIT) FILL(((tt & 1) ? SM_B1 : SM_B0), t + 2);
    }
#undef FILL

    if ((lane & 3) == 0) {
        g_bestval[split * BT + tokbase + tl0] = best0;
        g_bestval[split * BT + tokbase + tl1] = best1;
    }
}

// ================= kScan: threshold block maxes + exact fp32 rescore =================
__global__ void __launch_bounds__(128) kScan(const float* __restrict__ z,
                                             float* __restrict__ out, int out_size) {
    __shared__ int s_list[4][128];
    __shared__ int s_n[4];
    const int warp = threadIdx.x >> 5;
    const int lane = threadIdx.x & 31;
    const int token = blockIdx.x * 4 + warp;

    if (lane == 0) s_n[warp] = 0;
    __syncwarp();

    const float thr = fmaxf(g_bestval[token], g_bestval[BT + token]) - EPS;
    const uint4* bm = (const uint4*)(g_bmax + (size_t)token * NBLK);
#pragma unroll
    for (int q = 0; q < 4; q++) {
        uint4 u = bm[lane * 4 + q];
        uint32_t words[4] = {u.x, u.y, u.z, u.w};
#pragma unroll
        for (int k = 0; k < 4; k++) {
            __half2 h2 = *(__half2*)&words[k];
            float f0 = __low2float(h2), f1 = __high2float(h2);
            int blk0 = lane * 32 + q * 8 + k * 2;
            if (f0 > thr) { int p = atomicAdd(&s_n[warp], 1); if (p < 128) s_list[warp][p] = blk0; }
            if (f1 > thr) { int p = atomicAdd(&s_n[warp], 1); if (p < 128) s_list[warp][p] = blk0 + 1; }
        }
    }
    __syncwarp();
    int nc = s_n[warp]; if (nc > 128) nc = 128;

    float bestd = -1e30f;
    int   bidx  = 0x7fffffff;
    const float4* z4 = (const float4*)(z + (size_t)token * D);
    for (int ci = 0; ci < nc; ci++) {
        const int blk = s_list[warp][ci];
        if (lane < 16) {
            const int code = blk * 16 + lane;
            const float4* cr = (const float4*)(g_cn + (size_t)code * D);
            float d0 = 0.f, d1 = 0.f, d2 = 0.f, d3 = 0.f;
#pragma unroll
            for (int j = 0; j < 16; j++) {
                float4 b = cr[j];
                float4 a = __ldg(&z4[j]);
                d0 = fmaf(a.x, b.x, d0);
                d1 = fmaf(a.y, b.y, d1);
                d2 = fmaf(a.z, b.z, d2);
                d3 = fmaf(a.w, b.w, d3);
            }
            float dot = (d0 + d1) + (d2 + d3);
            if (dot > bestd || (dot == bestd && code < bidx)) { bestd = dot; bidx = code; }
        }
    }
#pragma unroll
    for (int off = 16; off; off >>= 1) {
        float ov = __shfl_xor_sync(0xFFFFFFFFu, bestd, off);
        int   oi = __shfl_xor_sync(0xFFFFFFFFu, bidx, off);
        if (ov > bestd || (ov == bestd && oi < bidx)) { bestd = ov; bidx = oi; }
    }
    if (lane == 0) {
        g_idx[token] = bidx;
        const int off = BT * D + 1 + token;
        if (off < out_size) out[off] = (float)bidx;
    }
}

// ================= kCD: gather quantized + MSE + finalize loss =================
__global__ void __launch_bounds__(256) kCD(const float* __restrict__ z,
                                           float* __restrict__ out, int out_size) {
    __shared__ float red[256];
    __shared__ int s_last;
    const int tid = threadIdx.x;
    const float4* z4 = (const float4*)z;
    const float4* q4 = (const float4*)g_qcb;
    float4* o4 = (float4*)out;

    float ps = 0.f;
#pragma unroll
    for (int i = 0; i < 8; i++) {
        int g = blockIdx.x * 2048 + i * 256 + tid;
        int token = g >> 4;
        int idx = g_idx[token];
        float4 q = q4[idx * 16 + (g & 15)];
        float4 zz = z4[g];
        if (g * 4 + 3 < out_size) o4[g] = q;
        float dx = q.x - zz.x, dy = q.y - zz.y;
        float dz_ = q.z - zz.z, dw = q.w - zz.w;
        ps += dx * dx + dy * dy + dz_ * dz_ + dw * dw;
    }
    red[tid] = ps;
    __syncthreads();
    for (int st = 128; st > 0; st >>= 1) {
        if (tid < st) red[tid] += red[tid + st];
        __syncthreads();
    }
    if (tid == 0) {
        g_partials[blockIdx.x] = red[0];
        __threadfence();
        int prev = atomicAdd(&g_done, 1);
        s_last = (prev == 127);
    }
    __syncthreads();
    if (s_last) {
        __threadfence();
        if (tid < 128) red[tid] = g_partials[tid];
        __syncthreads();
        for (int st = 64; st > 0; st >>= 1) {
            if (tid < st) red[tid] += red[tid + st];
            __syncthreads();
        }
        if (tid == 0) {
            float loss = 1.25f * red[0] / (float)(BT * D);
            if (BT * D < out_size) out[BT * D] = loss;
            g_done = 0;   // reset for next graph replay
        }
    }
}

// ================= launch =================
extern "C" void kernel_launch(void* const* d_in, const int* in_sizes, int n_in,
                              void* d_out, int out_size) {
    const float* z  = (const float*)d_in[0];
    const float* cb = (const float*)d_in[1];
    const float* pw = (const float*)d_in[2];
    const float* pb = (const float*)d_in[3];
    // d_in[4] = scale: positive constant, cannot change argmin or any output value.
    float* out = (float*)d_out;

    cudaFuncSetAttribute(kMain, cudaFuncAttributeMaxDynamicSharedMemorySize, SM_TOT);

    kPrep<<<NUM_EMB / 64, 256>>>(cb, pw, pb);
    dim3 gM(BT / M_TILE, NSPLIT);
    kMain<<<gM, 256, SM_TOT>>>(z);
    kScan<<<BT / 4, 128>>>(z, out, out_size);
    kCD<<<128, 256>>>(z, out, out_size);
}